// round 8
// baseline (speedup 1.0000x reference)
#include <cuda_runtime.h>
#include <math.h>
#include <stdint.h>

#define N_NODES   200000
#define NODE_DIM  256
#define OUT_DIM   512
#define NUM_HEADS 8
#define HEAD_DIM  32
#define HID       256
#define N_GRAPHS  2000

// ---------------- scratch (static device globals; no runtime allocation) ----
// Buffer reuse: Vwm aliases Hs_wm, Vws aliases Hs_ws (scores consume Hs_*
// before the value layer-2 GEMM writes V*; launches serialize on the stream).
__device__ float g_Hs_wm[(size_t)N_NODES * HID];   // later reused as Vwm
__device__ float g_Hv_wm[(size_t)N_NODES * HID];
__device__ float g_Hs_ws[(size_t)N_NODES * HID];   // later reused as Vws
__device__ float g_Hv_ws[(size_t)N_NODES * HID];
__device__ float g_Swm [(size_t)N_NODES * NUM_HEADS];
__device__ float g_Sws [(size_t)N_NODES * NUM_HEADS];
__device__ int   g_gstart[N_GRAPHS + 1];
__device__ int   g_seg64;
__device__ float g_Awm [(size_t)N_GRAPHS * HID];
__device__ float g_Aws [(size_t)N_GRAPHS * HID];
__device__ float g_Amax[(size_t)N_GRAPHS * HID];
__device__ float g_R   [(size_t)N_GRAPHS * 3 * OUT_DIM];

// ---------------- tf32 helpers ----------------------------------------------
__device__ __forceinline__ uint32_t f2tf32(float f) {
    uint32_t u;
    asm("cvt.rna.tf32.f32 %0, %1;" : "=r"(u) : "f"(f));
    return u;
}

__device__ __forceinline__ void mma_tf32(float* c, const uint32_t* a, const uint32_t* b) {
    asm volatile(
        "mma.sync.aligned.m16n8k8.row.col.f32.tf32.tf32.f32 "
        "{%0,%1,%2,%3}, {%4,%5,%6,%7}, {%8,%9}, {%0,%1,%2,%3};"
        : "+f"(c[0]), "+f"(c[1]), "+f"(c[2]), "+f"(c[3])
        : "r"(a[0]), "r"(a[1]), "r"(a[2]), "r"(a[3]), "r"(b[0]), "r"(b[1]));
}

// ---------------- multi-problem tensor-core GEMM -----------------------------
// Up to 4 independent problems sharing lda/ldw/ldc/M/K:
//   C[w][M,N] = op(A[w][M,K]) @ W[w][K,N] (+bias[w])
// BM=128, BN=128, BK=32; 256 threads = 8 warps (2m x 4n), warp tile 64x32.
// blockIdx.x = w * npw + n_block; blockIdx.y = m_block.
// Double-buffered dynamic smem (71.7 KB), one sync per k-tile, STS.128 stores.
struct GemmSet {
    const float* A[4];
    const float* W[4];
    const float* B[4];
    float*       C[4];
};

#define AS_W 36
#define BS_W 136
#define AS_SZ (128 * AS_W)   // 4608 words
#define BS_SZ (32 * BS_W)    // 4352 words

template<bool RELU_OUT, bool RELU_IN, bool HAS_BIAS>
__global__ __launch_bounds__(256)
void tgemm_multi(GemmSet set, int npw, int lda, int ldw, int ldc, int M, int K)
{
    extern __shared__ uint32_t smem[];
    uint32_t* Asm = smem;                 // [2][128][36]
    uint32_t* Bsm = smem + 2 * AS_SZ;     // [2][32][136]

    const int wsel = blockIdx.x / npw;
    const float* __restrict__ A    = set.A[wsel];
    const float* __restrict__ W    = set.W[wsel];
    const float* __restrict__ bias = set.B[wsel];
    float*       __restrict__ C    = set.C[wsel];

    const int tid   = threadIdx.x;
    const int lane  = tid & 31;
    const int wid   = tid >> 5;
    const int warpM = wid & 1;
    const int warpN = wid >> 1;
    const int g     = lane >> 2;
    const int t     = lane & 3;
    const int bm    = blockIdx.y * 128;
    const int bn    = (blockIdx.x % npw) * 128;

    float acc[4][4][4];
    #pragma unroll
    for (int mi = 0; mi < 4; mi++)
        #pragma unroll
        for (int ni = 0; ni < 4; ni++)
            #pragma unroll
            for (int q = 0; q < 4; q++) acc[mi][ni][q] = 0.0f;

    float4 pa[4], pb[4];
    const int arow = tid >> 3;          // 0..31
    const int acol = (tid & 7) * 4;     // 0..28
    const int bcol = lane * 4;          // 0..124

    auto LOAD = [&](int k0) {
        #pragma unroll
        for (int j = 0; j < 4; j++) {
            int grow = bm + j * 32 + arow; if (grow >= M) grow = M - 1;
            pa[j] = *reinterpret_cast<const float4*>(A + (size_t)grow * lda + k0 + acol);
        }
        #pragma unroll
        for (int j = 0; j < 4; j++) {
            int krow = j * 8 + wid;
            pb[j] = *reinterpret_cast<const float4*>(W + (size_t)(k0 + krow) * ldw + bn + bcol);
        }
    };

    auto STORE = [&](int s) {
        uint32_t* as = Asm + s * AS_SZ;
        uint32_t* bs = Bsm + s * BS_SZ;
        #pragma unroll
        for (int j = 0; j < 4; j++) {
            float4 v = pa[j];
            if (RELU_IN) {
                v.x = fmaxf(v.x, 0.f); v.y = fmaxf(v.y, 0.f);
                v.z = fmaxf(v.z, 0.f); v.w = fmaxf(v.w, 0.f);
            }
            uint4 u = make_uint4(f2tf32(v.x), f2tf32(v.y), f2tf32(v.z), f2tf32(v.w));
            *reinterpret_cast<uint4*>(as + (j * 32 + arow) * AS_W + acol) = u;
        }
        #pragma unroll
        for (int j = 0; j < 4; j++) {
            float4 v = pb[j];
            uint4 u = make_uint4(f2tf32(v.x), f2tf32(v.y), f2tf32(v.z), f2tf32(v.w));
            *reinterpret_cast<uint4*>(bs + (j * 8 + wid) * BS_W + bcol) = u;
        }
    };

    LOAD(0);
    STORE(0);
    if (K > 32) LOAD(32);
    __syncthreads();

    int s = 0;
    for (int k0 = 0; k0 < K; k0 += 32) {
        if (k0 + 32 < K) STORE(s ^ 1);
        if (k0 + 64 < K) LOAD(k0 + 64);

        const uint32_t* as = Asm + s * AS_SZ;
        const uint32_t* bs = Bsm + s * BS_SZ;
        #pragma unroll
        for (int kk = 0; kk < 4; kk++) {
            uint32_t af[4][4], bf[4][2];
            #pragma unroll
            for (int mi = 0; mi < 4; mi++) {
                int r0 = warpM * 64 + mi * 16;
                af[mi][0] = as[(r0 + g    ) * AS_W + kk * 8 + t    ];
                af[mi][1] = as[(r0 + 8 + g) * AS_W + kk * 8 + t    ];
                af[mi][2] = as[(r0 + g    ) * AS_W + kk * 8 + t + 4];
                af[mi][3] = as[(r0 + 8 + g) * AS_W + kk * 8 + t + 4];
            }
            #pragma unroll
            for (int ni = 0; ni < 4; ni++) {
                int c0 = warpN * 32 + ni * 8 + g;
                bf[ni][0] = bs[(kk * 8 + t    ) * BS_W + c0];
                bf[ni][1] = bs[(kk * 8 + t + 4) * BS_W + c0];
            }
            #pragma unroll
            for (int mi = 0; mi < 4; mi++)
                #pragma unroll
                for (int ni = 0; ni < 4; ni++)
                    mma_tf32(acc[mi][ni], af[mi], bf[ni]);
        }
        __syncthreads();
        s ^= 1;
    }

    // ---- epilogue
    #pragma unroll
    for (int mi = 0; mi < 4; mi++) {
        int row0 = bm + warpM * 64 + mi * 16 + g;
        #pragma unroll
        for (int ni = 0; ni < 4; ni++) {
            int col = bn + warpN * 32 + ni * 8 + 2 * t;
            float b0 = 0.f, b1 = 0.f;
            if (HAS_BIAS) { b0 = bias[col]; b1 = bias[col + 1]; }
            float2 v0, v1;
            v0.x = acc[mi][ni][0] + b0; v0.y = acc[mi][ni][1] + b1;
            v1.x = acc[mi][ni][2] + b0; v1.y = acc[mi][ni][3] + b1;
            if (RELU_OUT) {
                v0.x = fmaxf(v0.x, 0.f); v0.y = fmaxf(v0.y, 0.f);
                v1.x = fmaxf(v1.x, 0.f); v1.y = fmaxf(v1.y, 0.f);
            }
            if (row0 < M)
                *reinterpret_cast<float2*>(C + (size_t)row0 * ldc + col) = v0;
            if (row0 + 8 < M)
                *reinterpret_cast<float2*>(C + (size_t)(row0 + 8) * ldc + col) = v1;
        }
    }
}

// ---------------- score layer: S[N,8] = H[N,256] @ w2[256,8] + b2 ------------
__global__ __launch_bounds__(256)
void score_kernel(const float* __restrict__ H, const float* __restrict__ w2,
                  const float* __restrict__ b2, float* __restrict__ S)
{
    __shared__ float w2s[HID * NUM_HEADS];
    __shared__ float b2s[NUM_HEADS];
    int tid = threadIdx.x;
    for (int i = tid; i < HID * NUM_HEADS; i += 256) w2s[i] = w2[i];
    if (tid < NUM_HEADS) b2s[tid] = b2[tid];
    __syncthreads();

    int warp = tid >> 5, lane = tid & 31;
    int node = blockIdx.x * 8 + warp;
    if (node >= N_NODES) return;

    float acc[NUM_HEADS];
    #pragma unroll
    for (int j = 0; j < NUM_HEADS; j++) acc[j] = 0.f;

    const float* h = H + (size_t)node * HID;
    #pragma unroll
    for (int r = 0; r < 8; r++) {
        int k = r * 32 + lane;
        float hv = h[k];
        #pragma unroll
        for (int j = 0; j < NUM_HEADS; j++) acc[j] = fmaf(hv, w2s[k * NUM_HEADS + j], acc[j]);
    }
    #pragma unroll
    for (int j = 0; j < NUM_HEADS; j++) {
        float v = acc[j];
        #pragma unroll
        for (int off = 16; off; off >>= 1) v += __shfl_xor_sync(0xFFFFFFFFu, v, off);
        if (lane == j) S[(size_t)node * NUM_HEADS + j] = v + b2s[j];
    }
}

// ---------------- seg dtype detection (int64 vs int32) -----------------------
__global__ void detect_seg(const int* __restrict__ p32)
{
    if (blockIdx.x == 0 && threadIdx.x == 0) {
        int nz = 0;
        for (int i = 4000; i < 5000; i++) nz |= p32[2 * i + 1];
        g_seg64 = (nz == 0) ? 1 : 0;
    }
}

// ---------------- graph ranges (seg is sorted) -------------------------------
__global__ void graph_bounds(const void* __restrict__ segv)
{
    int g = blockIdx.x * blockDim.x + threadIdx.x;
    if (g > N_GRAPHS) return;
    if (g == N_GRAPHS) { g_gstart[g] = N_NODES; return; }
    const int is64 = g_seg64;
    const long long* p64 = (const long long*)segv;
    const int*       p32 = (const int*)segv;
    int lo = 0, hi = N_NODES;
    while (lo < hi) {
        int mid = (lo + hi) >> 1;
        long long v = is64 ? p64[mid] : (long long)p32[mid];
        if (v < (long long)g) lo = mid + 1; else hi = mid;
    }
    g_gstart[g] = lo;
}

// ---------------- per-graph accumulation (block per graph, 256 threads) ------
__global__ __launch_bounds__(256)
void accumulate_kernel(const float* __restrict__ X,
                       const float* __restrict__ Vwm,
                       const float* __restrict__ Vws)
{
    int g   = blockIdx.x;
    int s0  = g_gstart[g], s1 = g_gstart[g + 1];
    int tid = threadIdx.x;
    int n   = s1 - s0;

    __shared__ float red[32][NUM_HEADS];
    __shared__ float mh[NUM_HEADS], inv[NUM_HEADS];

    if (n == 0) {
        g_Awm [(size_t)g * HID + tid] = 0.f;
        g_Aws [(size_t)g * HID + tid] = 0.f;
        g_Amax[(size_t)g * HID + tid] = 0.f;
        return;
    }

    int h0 = tid & 7, grp = tid >> 3;
    float m = -INFINITY;
    for (int i = grp; i < n; i += 32)
        m = fmaxf(m, g_Swm[(size_t)(s0 + i) * NUM_HEADS + h0]);
    red[grp][h0] = m;
    __syncthreads();
    if (tid < NUM_HEADS) {
        float mm = -INFINITY;
        #pragma unroll
        for (int r = 0; r < 32; r++) mm = fmaxf(mm, red[r][tid]);
        mh[tid] = mm;
    }
    __syncthreads();
    float mloc = mh[h0];
    float se = 0.f;
    for (int i = grp; i < n; i += 32)
        se += __expf(g_Swm[(size_t)(s0 + i) * NUM_HEADS + h0] - mloc);
    red[grp][h0] = se;
    __syncthreads();
    if (tid < NUM_HEADS) {
        float s = 0.f;
        #pragma unroll
        for (int r = 0; r < 32; r++) s += red[r][tid];
        inv[tid] = 1.0f / s;
    }
    __syncthreads();

    int c = tid;
    int h = c >> 5;
    float mH = mh[h], invH = inv[h];
    float aw = 0.f, asum = 0.f, mx = -INFINITY;
    for (int i = s0; i < s1; i++) {
        float sw = g_Swm[(size_t)i * NUM_HEADS + h];
        float ww = __expf(sw - mH) * invH;
        float ss = g_Sws[(size_t)i * NUM_HEADS + h];
        float ws = 1.0f / (1.0f + __expf(-ss));
        aw   = fmaf(ww, Vwm[(size_t)i * HID + c], aw);
        asum = fmaf(ws, Vws[(size_t)i * HID + c], asum);
        mx   = fmaxf(mx, X[(size_t)i * HID + c]);
    }
    g_Awm [(size_t)g * HID + c] = aw;
    g_Aws [(size_t)g * HID + c] = asum;
    g_Amax[(size_t)g * HID + c] = mx;
}

// ---------------- launch -----------------------------------------------------
extern "C" void kernel_launch(void* const* d_in, const int* in_sizes, int n_in,
                              void* d_out, int out_size)
{
    const float* x   = (const float*)d_in[0];
    const void*  seg = d_in[1];

    int base = 2;
    if (n_in >= 23 || (n_in > 2 && in_sizes[2] == 1)) base = 3;

    const float* wm_sw1 = (const float*)d_in[base + 0];
    const float* wm_sb1 = (const float*)d_in[base + 1];
    const float* wm_sw2 = (const float*)d_in[base + 2];
    const float* wm_sb2 = (const float*)d_in[base + 3];
    const float* wm_vw1 = (const float*)d_in[base + 4];
    const float* wm_vb1 = (const float*)d_in[base + 5];
    const float* wm_vw2 = (const float*)d_in[base + 6];
    const float* wm_vb2 = (const float*)d_in[base + 7];
    const float* wm_cw  = (const float*)d_in[base + 8];
    const float* ws_sw1 = (const float*)d_in[base + 9];
    const float* ws_sb1 = (const float*)d_in[base + 10];
    const float* ws_sw2 = (const float*)d_in[base + 11];
    const float* ws_sb2 = (const float*)d_in[base + 12];
    const float* ws_vw1 = (const float*)d_in[base + 13];
    const float* ws_vb1 = (const float*)d_in[base + 14];
    const float* ws_vw2 = (const float*)d_in[base + 15];
    const float* ws_vb2 = (const float*)d_in[base + 16];
    const float* ws_cw  = (const float*)d_in[base + 17];
    const float* mx_cw  = (const float*)d_in[base + 18];
    const float* fin_w  = (const float*)d_in[base + 19];

    float *Hs_wm, *Hv_wm, *Hs_ws, *Hv_ws, *Awm, *Aws, *Amax, *R;
    cudaGetSymbolAddress((void**)&Hs_wm, g_Hs_wm);
    cudaGetSymbolAddress((void**)&Hv_wm, g_Hv_wm);
    cudaGetSymbolAddress((void**)&Hs_ws, g_Hs_ws);
    cudaGetSymbolAddress((void**)&Hv_ws, g_Hv_ws);
    cudaGetSymbolAddress((void**)&Awm,  g_Awm);
    cudaGetSymbolAddress((void**)&Aws,  g_Aws);
    cudaGetSymbolAddress((void**)&Amax, g_Amax);
    cudaGetSymbolAddress((void**)&R,    g_R);
    float* Swm; cudaGetSymbolAddress((void**)&Swm, g_Swm);
    float* Sws; cudaGetSymbolAddress((void**)&Sws, g_Sws);

    // Buffer reuse (safe: stream-ordered): V buffers alias dead Hs buffers.
    float* Vwm = Hs_wm;
    float* Vws = Hs_ws;

    const int SMEM = (2 * AS_SZ + 2 * BS_SZ) * 4;  // 71680 B
    cudaFuncSetAttribute(tgemm_multi<true,  false, true >, cudaFuncAttributeMaxDynamicSharedMemorySize, SMEM);
    cudaFuncSetAttribute(tgemm_multi<false, false, true >, cudaFuncAttributeMaxDynamicSharedMemorySize, SMEM);
    cudaFuncSetAttribute(tgemm_multi<false, false, false>, cudaFuncAttributeMaxDynamicSharedMemorySize, SMEM);
    cudaFuncSetAttribute(tgemm_multi<false, true,  false>, cudaFuncAttributeMaxDynamicSharedMemorySize, SMEM);

    const int MB_BIG = (N_NODES + 127) / 128;   // 1563
    const int MB_G   = (N_GRAPHS + 127) / 128;  // 16

    // ---- 1) fused node-phase layer-1: 4 GEMMs sharing A = x
    {
        GemmSet s;
        s.A[0] = x;      s.A[1] = x;      s.A[2] = x;      s.A[3] = x;
        s.W[0] = wm_sw1; s.W[1] = wm_vw1; s.W[2] = ws_sw1; s.W[3] = ws_vw1;
        s.B[0] = wm_sb1; s.B[1] = wm_vb1; s.B[2] = ws_sb1; s.B[3] = ws_vb1;
        s.C[0] = Hs_wm;  s.C[1] = Hv_wm;  s.C[2] = Hs_ws;  s.C[3] = Hv_ws;
        tgemm_multi<true, false, true><<<dim3(8, MB_BIG), 256, SMEM>>>(
            s, 2, NODE_DIM, HID, HID, N_NODES, NODE_DIM);
    }

    // ---- 2) score layers (consume Hs_*; afterwards those buffers are dead)
    score_kernel<<<N_NODES / 8, 256>>>(Hs_wm, wm_sw2, wm_sb2, Swm);
    score_kernel<<<N_NODES / 8, 256>>>(Hs_ws, ws_sw2, ws_sb2, Sws);

    // ---- 3) fused value layer-2: 2 GEMMs (write V* into reused Hs_* space)
    {
        GemmSet s;
        s.A[0] = Hv_wm;  s.A[1] = Hv_ws;  s.A[2] = Hv_wm;  s.A[3] = Hv_ws;
        s.W[0] = wm_vw2; s.W[1] = ws_vw2; s.W[2] = wm_vw2; s.W[3] = ws_vw2;
        s.B[0] = wm_vb2; s.B[1] = ws_vb2; s.B[2] = wm_vb2; s.B[3] = ws_vb2;
        s.C[0] = Vwm;    s.C[1] = Vws;    s.C[2] = Vwm;    s.C[3] = Vws;
        tgemm_multi<false, false, true><<<dim3(4, MB_BIG), 256, SMEM>>>(
            s, 2, HID, HID, HID, N_NODES, HID);
    }

    // ---- 4) segment reductions
    detect_seg<<<1, 32>>>((const int*)seg);
    graph_bounds<<<(N_GRAPHS + 256) / 256, 256>>>(seg);
    accumulate_kernel<<<N_GRAPHS, 256>>>(x, Vwm, Vws);

    // ---- 5) fused per-graph combines into R = [mean | sum | max]
    {
        GemmSet s;
        s.A[0] = Awm;   s.A[1] = Aws;   s.A[2] = Amax;  s.A[3] = Awm;
        s.W[0] = wm_cw; s.W[1] = ws_cw; s.W[2] = mx_cw; s.W[3] = wm_cw;
        s.B[0] = nullptr; s.B[1] = nullptr; s.B[2] = nullptr; s.B[3] = nullptr;
        s.C[0] = R;     s.C[1] = R + 512; s.C[2] = R + 1024; s.C[3] = R;
        tgemm_multi<false, false, false><<<dim3(12, MB_G), 256, SMEM>>>(
            s, 4, HID, OUT_DIM, 3 * OUT_DIM, N_GRAPHS, HID);
    }

    // ---- 6) final: out = relu(R) @ final_w
    {
        GemmSet s;
        s.A[0] = R;     s.A[1] = R;     s.A[2] = R;     s.A[3] = R;
        s.W[0] = fin_w; s.W[1] = fin_w; s.W[2] = fin_w; s.W[3] = fin_w;
        s.B[0] = nullptr; s.B[1] = nullptr; s.B[2] = nullptr; s.B[3] = nullptr;
        s.C[0] = (float*)d_out; s.C[1] = (float*)d_out; s.C[2] = (float*)d_out; s.C[3] = (float*)d_out;
        tgemm_multi<false, true, false><<<dim3(4, MB_G), 256, SMEM>>>(
            s, 4, 3 * OUT_DIM, OUT_DIM, OUT_DIM, N_GRAPHS, 3 * OUT_DIM);
    }
}